// round 17
// baseline (speedup 1.0000x reference)
#include <cuda_runtime.h>
#include <cuda_fp16.h>
#include <cstdint>

// STN flow-relative bilinear warp, two-pass with fp16 NHWC scratch:
//   pass 1: NCHW f32 -> NHWC fp16 scratch (R13 proven version)
//   pass 2: barrier-free cooperative gather, 128-thread blocks (64 px),
//           per-half interleaved setup/loads (setup-B ALU hides load-A
//           latency), float2 NCHW stores.

static constexpr int H  = 1024;
static constexpr int W  = 1024;
static constexpr int C  = 32;
static constexpr int HW = H * W;

// 64 MB scratch: x transposed to [H*W][C] in fp16 (mostly L2-resident)
__device__ __half g_xt[(size_t)HW * C];

// ---------------- pass 1: NCHW -> NHWC transpose + f32->fp16 ----------------
__device__ __forceinline__ int sw_addr(int c, int px) {
    return c * 128 + 4 * ((px >> 2) ^ (c >> 2)) + (px & 3);
}

__global__ __launch_bounds__(256) void transpose_kernel(const float* __restrict__ x)
{
    __shared__ float s[32 * 128];

    int tid = threadIdx.x;
    int p0  = blockIdx.x * 128;

#pragma unroll
    for (int i = 0; i < 4; ++i) {
        int j   = i * 256 + tid;
        int c   = j >> 5;
        int pxg = j & 31;
        float4 v = __ldcs((const float4*)(x + (size_t)c * HW + p0 + 4 * pxg));
        *(float4*)(s + c * 128 + 4 * (pxg ^ (c >> 2))) = v;
    }
    __syncthreads();

#pragma unroll
    for (int i = 0; i < 2; ++i) {
        int j  = i * 256 + tid;
        int pl = j >> 2;           // pixel 0..127
        int cg = j & 3;            // channel octet 0..3 (8 channels)
        int c0 = 8 * cg;
        __half2 h0 = __floats2half2_rn(s[sw_addr(c0 + 0, pl)], s[sw_addr(c0 + 1, pl)]);
        __half2 h1 = __floats2half2_rn(s[sw_addr(c0 + 2, pl)], s[sw_addr(c0 + 3, pl)]);
        __half2 h2 = __floats2half2_rn(s[sw_addr(c0 + 4, pl)], s[sw_addr(c0 + 5, pl)]);
        __half2 h3 = __floats2half2_rn(s[sw_addr(c0 + 6, pl)], s[sw_addr(c0 + 7, pl)]);
        uint4 v;
        v.x = *(const unsigned int*)&h0;
        v.y = *(const unsigned int*)&h1;
        v.z = *(const unsigned int*)&h2;
        v.w = *(const unsigned int*)&h3;
        *(uint4*)(g_xt + (size_t)(p0 + pl) * C + 8 * cg) = v;
    }
}

// ---------------- pass 2: barrier-free bilinear warp from fp16 NHWC ---------
// Block = 128 threads, 64 pixels. Thread = (pixel-pair, channel-octet).
struct Setup { int o0, o1, o2, o3; float w0, w1, w2, w3; };

__device__ __forceinline__ Setup pixel_setup(int p, float fx, float fy)
{
    int px = p & (W - 1);
    int py = p >> 10;              // W == 1024

    // Match reference math exactly (normalize + unnormalize round-trip)
    float gx = (fx + (float)px) * (2.0f / (float)(W - 1)) - 1.0f;
    float gy = (fy + (float)py) * (2.0f / (float)(H - 1)) - 1.0f;
    float ix = ((gx + 1.0f) * (float)W - 1.0f) * 0.5f;
    float iy = ((gy + 1.0f) * (float)H - 1.0f) * 0.5f;

    float x0f = floorf(ix);
    float y0f = floorf(iy);
    float wx1 = ix - x0f;
    float wy1 = iy - y0f;
    float wx0 = 1.0f - wx1;
    float wy0 = 1.0f - wy1;

    int x0 = (int)x0f;
    int y0 = (int)y0f;
    int x1 = x0 + 1;
    int y1 = y0 + 1;

    float vx0 = (x0 >= 0 && x0 < W) ? 1.0f : 0.0f;
    float vx1 = (x1 >= 0 && x1 < W) ? 1.0f : 0.0f;
    float vy0 = (y0 >= 0 && y0 < H) ? 1.0f : 0.0f;
    float vy1 = (y1 >= 0 && y1 < H) ? 1.0f : 0.0f;

    int cx0 = min(max(x0, 0), W - 1);
    int cx1 = min(max(x1, 0), W - 1);
    int cy0 = min(max(y0, 0), H - 1);
    int cy1 = min(max(y1, 0), H - 1);

    Setup s;
    s.w0 = wx0 * wy0 * vx0 * vy0;
    s.w1 = wx1 * wy0 * vx1 * vy0;
    s.w2 = wx0 * wy1 * vx0 * vy1;
    s.w3 = wx1 * wy1 * vx1 * vy1;
    s.o0 = cy0 * W + cx0;
    s.o1 = cy0 * W + cx1;
    s.o2 = cy1 * W + cx0;
    s.o3 = cy1 * W + cx1;
    return s;
}

__global__ __launch_bounds__(128) void warp_bilinear_coop_kernel(
    const float* __restrict__ flow,
    float* __restrict__ out)
{
    int tid = threadIdx.x;
    int p0  = blockIdx.x * 64;

    int pl = tid >> 2;                 // 0..31 -> pixels 2*pl, 2*pl+1
    int cg = tid & 3;                  // channel octet (0..3), 8 halves each
    int pbase = p0 + 2 * pl;

    // flow loads: 4 lanes of each pixel-pair share one 8B load (broadcast)
    float2 fx2 = __ldg((const float2*)(flow + pbase));
    float2 fy2 = __ldg((const float2*)(flow + HW + pbase));

    // ---- half A: setup, then issue loads immediately ----
    Setup sA = pixel_setup(pbase, fx2.x, fy2.x);
    uint4 vA0 = __ldg((const uint4*)(g_xt + (size_t)sA.o0 * C) + cg);
    uint4 vA1 = __ldg((const uint4*)(g_xt + (size_t)sA.o1 * C) + cg);
    uint4 vA2 = __ldg((const uint4*)(g_xt + (size_t)sA.o2 * C) + cg);
    uint4 vA3 = __ldg((const uint4*)(g_xt + (size_t)sA.o3 * C) + cg);

    // ---- half B: setup ALU overlaps half-A load latency ----
    Setup sB = pixel_setup(pbase + 1, fx2.y, fy2.y);
    uint4 vB0 = __ldg((const uint4*)(g_xt + (size_t)sB.o0 * C) + cg);
    uint4 vB1 = __ldg((const uint4*)(g_xt + (size_t)sB.o1 * C) + cg);
    uint4 vB2 = __ldg((const uint4*)(g_xt + (size_t)sB.o2 * C) + cg);
    uint4 vB3 = __ldg((const uint4*)(g_xt + (size_t)sB.o3 * C) + cg);

    float a[2][8];
#pragma unroll
    for (int half = 0; half < 2; ++half)
#pragma unroll
        for (int j = 0; j < 8; ++j) a[half][j] = 0.f;

    const uint4* vs[2][4] = {{&vA0, &vA1, &vA2, &vA3}, {&vB0, &vB1, &vB2, &vB3}};
    float wts[2][4] = {{sA.w0, sA.w1, sA.w2, sA.w3}, {sB.w0, sB.w1, sB.w2, sB.w3}};

#pragma unroll
    for (int half = 0; half < 2; ++half) {
#pragma unroll
        for (int k = 0; k < 4; ++k) {
            float w = wts[half][k];
            const uint4 vv = *vs[half][k];
            float2 f0 = __half22float2(*(const __half2*)&vv.x);
            float2 f1 = __half22float2(*(const __half2*)&vv.y);
            float2 f2 = __half22float2(*(const __half2*)&vv.z);
            float2 f3 = __half22float2(*(const __half2*)&vv.w);
            a[half][0] += w * f0.x;  a[half][1] += w * f0.y;
            a[half][2] += w * f1.x;  a[half][3] += w * f1.y;
            a[half][4] += w * f2.x;  a[half][5] += w * f2.y;
            a[half][6] += w * f3.x;  a[half][7] += w * f3.y;
        }
    }

    // float2 NCHW stores: channel 8*cg+j, adjacent pixel pair.
    float* ob = out + (size_t)(cg * 8) * HW + pbase;
#pragma unroll
    for (int j = 0; j < 8; ++j) {
        float2 st = make_float2(a[0][j], a[1][j]);
        __stcs((float2*)(ob + (size_t)j * HW), st);
    }
}

extern "C" void kernel_launch(void* const* d_in, const int* in_sizes, int n_in,
                              void* d_out, int out_size)
{
    const float* flow = (const float*)d_in[0];   // [1,2,H,W]
    const float* x    = (const float*)d_in[1];   // [1,C,H,W]
    float* out        = (float*)d_out;           // [1,C,H,W]

    (void)in_sizes; (void)n_in; (void)out_size;

    transpose_kernel<<<HW / 128, 256>>>(x);
    warp_bilinear_coop_kernel<<<HW / 64, 128>>>(flow, out);
}